// round 9
// baseline (speedup 1.0000x reference)
#include <cuda_runtime.h>
#include <cuda_bf16.h>
#include <math.h>

// Problem constants
#define SQ   1024
#define DIM  7168
#define NH   128
#define DNOPE 128
#define DROPE 64
#define DVAL 128
#define DQH  192         // DNOPE + DROPE
#define RQ   1536
#define RKV  512
#define HDQ  (NH*DQH)            // 24576
#define HKV  (NH*(DNOPE+DVAL))   // 32768
#define HDV  (NH*DVAL)           // 16384
#define EPS  1e-6f
#define NCAT 2176                // RQ + RKV + DROPE = 2112, padded to 17*128

// Scratch (device globals: allocation-free per harness rules; zero-init -> pads stay 0)
__device__ float g_hid  [SQ*DIM];
__device__ float g_wqkva[NCAT*DIM];
__device__ float g_qkva [SQ*NCAT];
__device__ float g_qan  [SQ*RQ];
__device__ float g_wqb  [HDQ*RQ];
__device__ float g_q    [SQ*HDQ];
__device__ float g_kvn  [SQ*RKV];
__device__ float g_wkvb [HKV*RKV];
__device__ float g_kv   [SQ*HKV];
__device__ float g_kpe  [SQ*DROPE];
__device__ float g_ao   [SQ*HDV];
__device__ float g_wo   [DIM*HDV];

// ---------------------------------------------------------------------------
// helpers
// ---------------------------------------------------------------------------
__device__ __forceinline__ unsigned f2tf(float f) {
  unsigned u;
  asm("cvt.rna.tf32.f32 %0, %1;" : "=r"(u) : "f"(f));
  return u;
}
__device__ __forceinline__ float rtf(float f) { return __uint_as_float(f2tf(f)); }

__device__ __forceinline__ unsigned smem_u32(const void* p){
  unsigned a;
  asm("{ .reg .u64 t; cvta.to.shared.u64 t, %1; cvt.u32.u64 %0, t; }" : "=r"(a) : "l"(p));
  return a;
}
__device__ __forceinline__ void cp16(unsigned dst, const float* src){
  asm volatile("cp.async.cg.shared.global [%0], [%1], 16;" :: "r"(dst), "l"(src));
}
__device__ __forceinline__ void cp_commit(){ asm volatile("cp.async.commit_group;" ::: "memory"); }
__device__ __forceinline__ void cp_wait1(){ asm volatile("cp.async.wait_group 1;" ::: "memory"); }

__device__ __forceinline__ void mma_tf32(float* d, const unsigned* a, const unsigned* b) {
  asm volatile(
    "mma.sync.aligned.m16n8k8.row.col.f32.tf32.tf32.f32 "
    "{%0,%1,%2,%3},{%4,%5,%6,%7},{%8,%9},{%0,%1,%2,%3};"
    : "+f"(d[0]), "+f"(d[1]), "+f"(d[2]), "+f"(d[3])
    : "r"(a[0]), "r"(a[1]), "r"(a[2]), "r"(a[3]), "r"(b[0]), "r"(b[1]));
}

// elementwise tf32 rounding (float4 vectorized); n4 = n/4
__global__ void __launch_bounds__(256) round4_kernel(
    const float4* __restrict__ src, float4* __restrict__ dst, int n4) {
  int i = blockIdx.x * 256 + threadIdx.x;
  if (i < n4) {
    float4 v = src[i];
    dst[i] = make_float4(rtf(v.x), rtf(v.y), rtf(v.z), rtf(v.w));
  }
}

// ---------------------------------------------------------------------------
// TF32 tensor-core NT GEMM, cp.async 3-stage ring, BK=32 per stage.
// C[M,N] = A[M,K] * B[N,K]^T, row-major, operands PRE-ROUNDED to tf32 values.
// CTA tile 128x128x32, 256 threads, warp tile 64x32 (m16n8k8).
// Requires M%128==0, N%128==0, K%32==0, K>=64.
// smem: 3 stages x (A 16KB + B 16KB) = 96KB dynamic; 2 CTAs/SM (192KB).
// Layout: 128B rows (32 words), 16B chunks XOR-swizzled: chunk ^= (row & 7).
// Fragment LDS (lanes g=0..7 x tig=0..3) then covers all 32 banks.
// ---------------------------------------------------------------------------
#define GSTAGES 3
#define STAGE_BYTES 32768                 // A 16KB + B 16KB
#define STAGE_WORDS 8192
#define GEMM_SMEM (GSTAGES*STAGE_BYTES)   // 98304

__global__ void __launch_bounds__(256, 2) gemm_tf32_cp(
    const float* __restrict__ A, const float* __restrict__ B,
    float* __restrict__ C, int M, int N, int K) {
  extern __shared__ unsigned sm[];
  const int KT = K >> 5;                  // stages of K=32
  const int bm = blockIdx.x * 128;
  const int bn = blockIdx.y * 128;
  const int tid  = threadIdx.x;
  const int lane = tid & 31;
  const int w    = tid >> 5;
  const int wm   = (w & 1) * 64;
  const int wn   = (w >> 1) * 32;
  const int g    = lane >> 2;
  const int tig  = lane & 3;

  // staging: thread t -> row = t>>1, chunks (t&1)*4 .. +3 (16B each), per operand
  const int srow = tid >> 1;              // 0..127
  const int ch0  = (tid & 1) * 4;         // 0 or 4
  const float* gA = A + (size_t)(bm + srow) * K + ch0 * 4;
  const float* gB = B + (size_t)(bn + srow) * K + ch0 * 4;
  const unsigned sb = smem_u32(sm);
  unsigned dOff[4];
#pragma unroll
  for (int i = 0; i < 4; i++)
    dOff[i] = (unsigned)(srow * 128 + (((ch0 + i) ^ (srow & 7)) << 4));

  auto fill = [&](int s, int kt) {
    const unsigned ab = sb + (unsigned)s * STAGE_BYTES;
    const unsigned bb = ab + 16384;
    const size_t k0 = (size_t)kt * 32;
#pragma unroll
    for (int i = 0; i < 4; i++) cp16(ab + dOff[i], gA + k0 + i * 4);
#pragma unroll
    for (int i = 0; i < 4; i++) cp16(bb + dOff[i], gB + k0 + i * 4);
  };

  // fragment address precompute (word offsets within a stage's A/B region)
  int abase0[4], abase1[4], ax[4], bbase[4], bx[4];
#pragma unroll
  for (int mt = 0; mt < 4; mt++) {
    const int r0 = wm + mt * 16 + g;      // rows r0 and r0+8 share (r&7)
    abase0[mt] = r0 * 32 + tig;
    abase1[mt] = (r0 + 8) * 32 + tig;
    ax[mt] = r0 & 7;
  }
#pragma unroll
  for (int nt = 0; nt < 4; nt++) {
    const int cn = wn + nt * 8 + g;
    bbase[nt] = cn * 32 + tig;
    bx[nt] = cn & 7;
  }

  float acc[4][4][4];
#pragma unroll
  for (int mt = 0; mt < 4; mt++)
#pragma unroll
    for (int nt = 0; nt < 4; nt++)
#pragma unroll
      for (int i = 0; i < 4; i++) acc[mt][nt][i] = 0.f;

  // prologue: stages 0,1
  fill(0, 0); cp_commit();
  fill(1, 1); cp_commit();

  int cs = 0;                             // compute stage = kt % 3
  int fs = 2;                             // fill stage = (kt+2) % 3
  for (int kt = 0; kt < KT; ++kt) {
    cp_wait1();                           // stage kt's group complete
    __syncthreads();                      // data visible + prev compute done
    if (kt + 2 < KT) fill(fs, kt + 2);
    cp_commit();

    const unsigned aB = (unsigned)cs * STAGE_WORDS;
    const unsigned bB = aB + 4096;
#pragma unroll
    for (int ks = 0; ks < 4; ++ks) {      // 4 x K=8 within the 32-K stage
      const int c0 = 2 * ks;              // chunk of k=kb+tig
      unsigned af[4][4], bf[4][2];
#pragma unroll
      for (int mt = 0; mt < 4; mt++) {
        af[mt][0] = sm[aB + abase0[mt] + (((c0    ) ^ ax[mt]) << 2)];
        af[mt][1] = sm[aB + abase1[mt] + (((c0    ) ^ ax[mt]) << 2)];
        af[mt][2] = sm[aB + abase0[mt] + (((c0 + 1) ^ ax[mt]) << 2)];
        af[mt][3] = sm[aB + abase1[mt] + (((c0 + 1) ^ ax[mt]) << 2)];
      }
#pragma unroll
      for (int nt = 0; nt < 4; nt++) {
        bf[nt][0] = sm[bB + bbase[nt] + (((c0    ) ^ bx[nt]) << 2)];
        bf[nt][1] = sm[bB + bbase[nt] + (((c0 + 1) ^ bx[nt]) << 2)];
      }
#pragma unroll
      for (int mt = 0; mt < 4; mt++)
#pragma unroll
        for (int nt = 0; nt < 4; nt++)
          mma_tf32(acc[mt][nt], af[mt], bf[nt]);
    }

    cs = (cs == 2) ? 0 : cs + 1;
    fs = (fs == 2) ? 0 : fs + 1;
  }

  // epilogue
#pragma unroll
  for (int mt = 0; mt < 4; mt++) {
    const int row = bm + wm + mt * 16 + g;
#pragma unroll
    for (int nt = 0; nt < 4; nt++) {
      const int col = bn + wn + nt * 8 + 2 * tig;
      *(float2*)(C + (size_t)row * N + col)       = make_float2(acc[mt][nt][0], acc[mt][nt][1]);
      *(float2*)(C + (size_t)(row + 8) * N + col) = make_float2(acc[mt][nt][2], acc[mt][nt][3]);
    }
  }
}

// ---------------------------------------------------------------------------
// RMSNorm: out = x * rsqrt(mean(x^2)+eps) * w, rounded to tf32 for next GEMM.
// ---------------------------------------------------------------------------
__global__ void __launch_bounds__(256) rmsnorm_kernel(
    const float* __restrict__ in, const float* __restrict__ w,
    float* __restrict__ out, int n, int istride, int ostride) {
  const int row = blockIdx.x;
  const float* x = in + (size_t)row * istride;
  float s = 0.f;
  for (int i = threadIdx.x; i < n; i += 256) { float v = x[i]; s += v*v; }
  __shared__ float red[256];
  red[threadIdx.x] = s;
  __syncthreads();
  for (int off = 128; off > 0; off >>= 1) {
    if (threadIdx.x < off) red[threadIdx.x] += red[threadIdx.x + off];
    __syncthreads();
  }
  const float inv = rsqrtf(red[0] / (float)n + EPS);
  float* o = out + (size_t)row * ostride;
  for (int i = threadIdx.x; i < n; i += 256) o[i] = rtf(x[i] * inv * w[i]);
}

// ---------------------------------------------------------------------------
// RoPE on q_pe (in-place in g_q).
// ---------------------------------------------------------------------------
__global__ void rope_q_kernel(float* __restrict__ q,
                              const float* __restrict__ cosb,
                              const float* __restrict__ sinb) {
  int idx = blockIdx.x * blockDim.x + threadIdx.x;   // SQ*NH*32
  int d = idx & 31;
  int h = (idx >> 5) & (NH - 1);
  int s = idx >> 12;
  float* base = q + (size_t)s * HDQ + h * DQH + DNOPE;
  float x1 = base[d], x2 = base[d + 32];
  float c1 = cosb[s*DROPE + d],      s1 = sinb[s*DROPE + d];
  float c2 = cosb[s*DROPE + d + 32], s2 = sinb[s*DROPE + d + 32];
  base[d]      = x1*c1 - x2*s1;
  base[d + 32] = x2*c2 + x1*s2;
}

// RoPE on k_pe (from qkva cols [2048, 2112)) -> g_kpe[S, 64]
__global__ void rope_k_kernel(const float* __restrict__ qkva,
                              const float* __restrict__ cosb,
                              const float* __restrict__ sinb,
                              float* __restrict__ kpe) {
  int idx = blockIdx.x * blockDim.x + threadIdx.x;  // SQ*32
  int d = idx & 31;
  int s = idx >> 5;
  float x1 = qkva[(size_t)s*NCAT + (RQ+RKV) + d];
  float x2 = qkva[(size_t)s*NCAT + (RQ+RKV) + 32 + d];
  float c1 = cosb[s*DROPE + d],      s1 = sinb[s*DROPE + d];
  float c2 = cosb[s*DROPE + d + 32], s2 = sinb[s*DROPE + d + 32];
  kpe[s*DROPE + d]      = x1*c1 - x2*s1;
  kpe[s*DROPE + 32 + d] = x2*c2 + x1*s2;
}

// ---------------------------------------------------------------------------
// Flash attention (causal), one block per (head, 64-row q tile), 256 threads.
// Output rounded to tf32 (feeds the wo GEMM).
// ---------------------------------------------------------------------------
#define QK_STR 193
#define PS_STR 65
#define FLASH_SMEM ((2*64*QK_STR + 64*128 + 64*PS_STR) * 4)

__global__ void __launch_bounds__(256) flash_kernel(
    const float* __restrict__ q, const float* __restrict__ kv,
    const float* __restrict__ kpe, float* __restrict__ ao) {
  extern __shared__ float smf[];
  float* Qs = smf;                     // 64 x QK_STR
  float* Ks = Qs + 64*QK_STR;          // 64 x QK_STR
  float* Vs = Ks + 64*QK_STR;          // 64 x 128
  float* Ps = Vs + 64*128;             // 64 x PS_STR

  const int h  = blockIdx.x;
  const int q0 = blockIdx.y * 64;
  const int tid = threadIdx.x;
  const int r = tid >> 2;
  const int g = tid & 3;

  for (int idx = tid; idx < 64*DQH; idx += 256) {
    int row = idx / DQH, d = idx % DQH;
    Qs[row*QK_STR + d] = q[(size_t)(q0+row)*HDQ + h*DQH + d];
  }

  float m = -INFINITY, l = 0.f;
  float o[32];
#pragma unroll
  for (int c = 0; c < 32; c++) o[c] = 0.f;
  const float scale = rsqrtf((float)DQH);

  const int nkt = blockIdx.y + 1;
  for (int kt = 0; kt < nkt; kt++) {
    const int k0 = kt * 64;
    __syncthreads();
    for (int idx = tid; idx < 64*DQH; idx += 256) {
      int row = idx / DQH, d = idx % DQH;
      Ks[row*QK_STR + d] = (d < DNOPE)
          ? kv[(size_t)(k0+row)*HKV + h*(DNOPE+DVAL) + d]
          : kpe[(k0+row)*DROPE + (d - DNOPE)];
    }
    for (int idx = tid; idx < 64*128; idx += 256) {
      int row = idx >> 7, d = idx & 127;
      Vs[idx] = kv[(size_t)(k0+row)*HKV + h*(DNOPE+DVAL) + DNOPE + d];
    }
    __syncthreads();

    float sc[16];
#pragma unroll
    for (int j = 0; j < 16; j++) sc[j] = 0.f;
    const float* qr = Qs + r*QK_STR;
    for (int d0 = 0; d0 < DQH; d0 += 8) {
      float qd[8];
#pragma unroll
      for (int dd = 0; dd < 8; dd++) qd[dd] = qr[d0+dd];
#pragma unroll
      for (int j = 0; j < 16; j++) {
        const float* kr = Ks + (g*16+j)*QK_STR + d0;
#pragma unroll
        for (int dd = 0; dd < 8; dd++) sc[j] += qd[dd]*kr[dd];
      }
    }
#pragma unroll
    for (int j = 0; j < 16; j++) {
      int c = g*16 + j;
      sc[j] = (k0 + c <= q0 + r) ? sc[j]*scale : -INFINITY;
    }

    float mloc = -INFINITY;
#pragma unroll
    for (int j = 0; j < 16; j++) mloc = fmaxf(mloc, sc[j]);
    mloc = fmaxf(mloc, __shfl_xor_sync(0xffffffffu, mloc, 1));
    mloc = fmaxf(mloc, __shfl_xor_sync(0xffffffffu, mloc, 2));
    float mnew = fmaxf(m, mloc);
    float alpha = expf(m - mnew);
    float lloc = 0.f;
#pragma unroll
    for (int j = 0; j < 16; j++) {
      float p = expf(sc[j] - mnew);
      lloc += p;
      Ps[r*PS_STR + g*16 + j] = p;
    }
    lloc += __shfl_xor_sync(0xffffffffu, lloc, 1);
    lloc += __shfl_xor_sync(0xffffffffu, lloc, 2);
    l = l * alpha + lloc;
    m = mnew;
#pragma unroll
    for (int c = 0; c < 32; c++) o[c] *= alpha;

    __syncwarp();
    const float* psr = Ps + r*PS_STR;
    for (int j = 0; j < 64; j++) {
      float pj = psr[j];
      const float* vr = Vs + j*128 + g;
#pragma unroll
      for (int c = 0; c < 32; c++) o[c] += pj * vr[4*c];
    }
  }

  const float invl = 1.f / l;
#pragma unroll
  for (int c = 0; c < 32; c++)
    ao[(size_t)(q0+r)*HDV + h*DVAL + g + 4*c] = rtf(o[c] * invl);
}

// ---------------------------------------------------------------------------
extern "C" void kernel_launch(void* const* d_in, const int* in_sizes, int n_in,
                              void* d_out, int out_size) {
  const float* hidden  = (const float*)d_in[0];
  const float* cosb    = (const float*)d_in[1];
  const float* sinb    = (const float*)d_in[2];
  const float* wq_a    = (const float*)d_in[3];
  const float* q_ln_w  = (const float*)d_in[4];
  const float* wq_b    = (const float*)d_in[5];
  const float* wkv_a   = (const float*)d_in[6];
  const float* kv_ln_w = (const float*)d_in[7];
  const float* wkv_b   = (const float*)d_in[8];
  const float* wo      = (const float*)d_in[9];
  float* out = (float*)d_out;

  float *hid, *wqkva, *qkva, *qan, *wqb, *q, *kvn, *wkvb, *kv, *kpe, *ao, *woR;
  cudaGetSymbolAddress((void**)&hid,   g_hid);
  cudaGetSymbolAddress((void**)&wqkva, g_wqkva);
  cudaGetSymbolAddress((void**)&qkva,  g_qkva);
  cudaGetSymbolAddress((void**)&qan,   g_qan);
  cudaGetSymbolAddress((void**)&wqb,   g_wqb);
  cudaGetSymbolAddress((void**)&q,     g_q);
  cudaGetSymbolAddress((void**)&kvn,   g_kvn);
  cudaGetSymbolAddress((void**)&wkvb,  g_wkvb);
  cudaGetSymbolAddress((void**)&kv,    g_kv);
  cudaGetSymbolAddress((void**)&kpe,   g_kpe);
  cudaGetSymbolAddress((void**)&ao,    g_ao);
  cudaGetSymbolAddress((void**)&woR,   g_wo);

  cudaFuncSetAttribute(gemm_tf32_cp, cudaFuncAttributeMaxDynamicSharedMemorySize, GEMM_SMEM);
  cudaFuncSetAttribute(flash_kernel, cudaFuncAttributeMaxDynamicSharedMemorySize, FLASH_SMEM);

  // pre-round operands to tf32 values (rna), re-layout wq_a||wkv_a into padded concat
  auto rnd = [](const float* s, float* d, int n) {
    round4_kernel<<<(n/4 + 255)/256, 256>>>((const float4*)s, (float4*)d, n/4);
  };
  rnd(hidden, hid,   SQ*DIM);
  rnd(wq_a,   wqkva, RQ*DIM);
  rnd(wkv_a,  wqkva + (size_t)RQ*DIM, (RKV+DROPE)*DIM);   // rows 2112..2175 stay 0
  rnd(wq_b,   wqb,   HDQ*RQ);
  rnd(wkv_b,  wkvb,  HKV*RKV);
  rnd(wo,     woR,   DIM*HDV);

  // fused q_a + kv_a projection: qkva[1024, 2176]
  gemm_tf32_cp<<<dim3(SQ/128, NCAT/128), 256, GEMM_SMEM>>>(hid, wqkva, qkva, SQ, NCAT, DIM);

  // q path
  rmsnorm_kernel<<<SQ, 256>>>(qkva, q_ln_w, qan, RQ, NCAT, RQ);
  gemm_tf32_cp<<<dim3(SQ/128, HDQ/128), 256, GEMM_SMEM>>>(qan, wqb, q, SQ, HDQ, RQ);

  // kv path
  rmsnorm_kernel<<<SQ, 256>>>(qkva + RQ, kv_ln_w, kvn, RKV, NCAT, RKV);
  gemm_tf32_cp<<<dim3(SQ/128, HKV/128), 256, GEMM_SMEM>>>(kvn, wkvb, kv, SQ, HKV, RKV);

  // RoPE
  rope_q_kernel<<<(SQ*NH*32)/256, 256>>>(q, cosb, sinb);
  rope_k_kernel<<<(SQ*32)/256, 256>>>(qkva, cosb, sinb, kpe);

  // causal flash attention (rounds its output)
  flash_kernel<<<dim3(NH, SQ/64), 256, FLASH_SMEM>>>(q, kv, kpe, ao);

  // output projection
  gemm_tf32_cp<<<dim3(SQ/128, DIM/128), 256, GEMM_SMEM>>>(ao, woR, out, SQ, DIM, HDV);
}

// round 11
// speedup vs baseline: 1.3391x; 1.3391x over previous
#include <cuda_runtime.h>
#include <cuda_bf16.h>
#include <math.h>

// Problem constants
#define SQ   1024
#define DIM  7168
#define NH   128
#define DNOPE 128
#define DROPE 64
#define DVAL 128
#define DQH  192         // DNOPE + DROPE
#define RQ   1536
#define RKV  512
#define HDQ  (NH*DQH)            // 24576
#define HKV  (NH*(DNOPE+DVAL))   // 32768
#define HDV  (NH*DVAL)           // 16384
#define EPS  1e-6f
#define NCAT 2176                // RQ + RKV + DROPE = 2112, padded to 17*128

// Scratch (device globals: allocation-free per harness rules; zero-init -> pads stay 0)
__device__ float g_hid  [SQ*DIM];
__device__ float g_wqkva[NCAT*DIM];
__device__ float g_qkva [SQ*NCAT];
__device__ float g_qan  [SQ*RQ];
__device__ float g_wqb  [HDQ*RQ];
__device__ float g_q    [SQ*HDQ];
__device__ float g_kvn  [SQ*RKV];
__device__ float g_wkvb [HKV*RKV];
__device__ float g_kv   [SQ*HKV];
__device__ float g_kpe  [SQ*DROPE];
__device__ float g_ao   [SQ*HDV];
__device__ float g_wo   [DIM*HDV];

// ---------------------------------------------------------------------------
// helpers
// ---------------------------------------------------------------------------
__device__ __forceinline__ unsigned f2tf(float f) {
  unsigned u;
  asm("cvt.rna.tf32.f32 %0, %1;" : "=r"(u) : "f"(f));
  return u;
}
__device__ __forceinline__ float rtf(float f) { return __uint_as_float(f2tf(f)); }

__device__ __forceinline__ unsigned smem_u32(const void* p){
  unsigned a;
  asm("{ .reg .u64 t; cvta.to.shared.u64 t, %1; cvt.u32.u64 %0, t; }" : "=r"(a) : "l"(p));
  return a;
}
__device__ __forceinline__ void cp16(unsigned dst, const float* src){
  asm volatile("cp.async.cg.shared.global [%0], [%1], 16;" :: "r"(dst), "l"(src));
}
__device__ __forceinline__ void cp_commit(){ asm volatile("cp.async.commit_group;" ::: "memory"); }
__device__ __forceinline__ void cp_wait2(){ asm volatile("cp.async.wait_group 2;" ::: "memory"); }

__device__ __forceinline__ void mma_tf32(float* d, const unsigned* a, const unsigned* b) {
  asm volatile(
    "mma.sync.aligned.m16n8k8.row.col.f32.tf32.tf32.f32 "
    "{%0,%1,%2,%3},{%4,%5,%6,%7},{%8,%9},{%0,%1,%2,%3};"
    : "+f"(d[0]), "+f"(d[1]), "+f"(d[2]), "+f"(d[3])
    : "r"(a[0]), "r"(a[1]), "r"(a[2]), "r"(a[3]), "r"(b[0]), "r"(b[1]));
}

// elementwise tf32 rounding (float4 vectorized); n4 = n/4
__global__ void __launch_bounds__(256) round4_kernel(
    const float4* __restrict__ src, float4* __restrict__ dst, int n4) {
  int i = blockIdx.x * 256 + threadIdx.x;
  if (i < n4) {
    float4 v = src[i];
    dst[i] = make_float4(rtf(v.x), rtf(v.y), rtf(v.z), rtf(v.w));
  }
}

// ---------------------------------------------------------------------------
// TF32 tensor-core NT GEMM, cp.async 4-stage pipeline (R6-proven config).
// C[M,N] = A[M,K] * B[N,K]^T, row-major, operands PRE-ROUNDED to tf32 values.
// CTA tile 128x128x16, 256 threads, warp tile 64x32 (m16n8k8).
// Requires M%128==0, N%128==0, K%16==0, K>=64.
// smem: 4 stages x (A 8KB + B 8KB) = 64KB dynamic. XOR swizzle:
//   word(row,k) = row*16 + ((k>>2) ^ ((row^(row>>2))&3))*4 + (k&3)
// ---------------------------------------------------------------------------
#define STAGES 4
#define AW 2048   // words per stage per operand (128 rows * 16 k)

__global__ void __launch_bounds__(256, 2) gemm_tf32_cp(
    const float* __restrict__ A, const float* __restrict__ B,
    float* __restrict__ C, int M, int N, int K) {
  extern __shared__ unsigned sm[];
  const int KT = K >> 4;
  const int bm = blockIdx.x * 128;
  const int bn = blockIdx.y * 128;
  const int tid  = threadIdx.x;
  const int lane = tid & 31;
  const int w    = tid >> 5;
  const int wm   = (w & 1) * 64;
  const int wn   = (w >> 1) * 32;
  const int g    = lane >> 2;
  const int tig  = lane & 3;

  // staging: thread -> 2 A chunks + 2 B chunks (16B each) per stage
  const int sr = tid >> 2;        // 0..63
  const int kc = tid & 3;         // chunk (4 k-values)
  const float* gA0 = A + (size_t)(bm + sr) * K + kc * 4;
  const float* gA1 = gA0 + (size_t)64 * K;
  const float* gB0 = B + (size_t)(bn + sr) * K + kc * 4;
  const float* gB1 = gB0 + (size_t)64 * K;
  const unsigned sb = smem_u32(sm);
  #define SWZ(r) (((r) ^ ((r) >> 2)) & 3)
  const unsigned dA0 = sb + 4u * ( sr      * 16 + ((kc ^ SWZ(sr))      << 2) );
  const unsigned dA1 = sb + 4u * ((sr + 64)* 16 + ((kc ^ SWZ(sr + 64)) << 2) );
  const unsigned dB0 = dA0 + 4u * STAGES * AW;
  const unsigned dB1 = dA1 + 4u * STAGES * AW;

  // fragment address precompute (word offsets; chunk xor applied inline)
  int aoff0[4], aoff1[4], asz0[4], asz1[4], boff[4], bsz[4];
#pragma unroll
  for (int mt = 0; mt < 4; mt++) {
    int r0 = wm + mt * 16 + g, r1 = r0 + 8;
    aoff0[mt] = r0 * 16 + tig; asz0[mt] = SWZ(r0);
    aoff1[mt] = r1 * 16 + tig; asz1[mt] = SWZ(r1);
  }
#pragma unroll
  for (int nt = 0; nt < 4; nt++) {
    int cn = wn + nt * 8 + g;
    boff[nt] = cn * 16 + tig; bsz[nt] = SWZ(cn);
  }

  float acc[4][4][4];
#pragma unroll
  for (int mt = 0; mt < 4; mt++)
#pragma unroll
    for (int nt = 0; nt < 4; nt++)
#pragma unroll
      for (int i = 0; i < 4; i++) acc[mt][nt][i] = 0.f;

  auto issue = [&](int s) {
    if (s < KT) {
      const unsigned so = ((unsigned)(s & 3) * AW) << 2;
      const size_t go = (size_t)s * 16;
      cp16(dA0 + so, gA0 + go);
      cp16(dA1 + so, gA1 + go);
      cp16(dB0 + so, gB0 + go);
      cp16(dB1 + so, gB1 + go);
    }
    cp_commit();
  };
  issue(0); issue(1); issue(2);

  for (int kt = 0; kt < KT; ++kt) {
    cp_wait2();
    __syncthreads();
    issue(kt + 3);
    const unsigned aB = (unsigned)(kt & 3) * AW;
    const unsigned bB = STAGES * AW + (unsigned)(kt & 3) * AW;
#pragma unroll
    for (int ks = 0; ks < 2; ++ks) {
      const int kc0 = ks << 1;
      unsigned af[4][4], bf[4][2];
#pragma unroll
      for (int mt = 0; mt < 4; mt++) {
        af[mt][0] = sm[aB + aoff0[mt] + (((kc0    ) ^ asz0[mt]) << 2)];
        af[mt][1] = sm[aB + aoff1[mt] + (((kc0    ) ^ asz1[mt]) << 2)];
        af[mt][2] = sm[aB + aoff0[mt] + (((kc0 + 1) ^ asz0[mt]) << 2)];
        af[mt][3] = sm[aB + aoff1[mt] + (((kc0 + 1) ^ asz1[mt]) << 2)];
      }
#pragma unroll
      for (int nt = 0; nt < 4; nt++) {
        bf[nt][0] = sm[bB + boff[nt] + (((kc0    ) ^ bsz[nt]) << 2)];
        bf[nt][1] = sm[bB + boff[nt] + (((kc0 + 1) ^ bsz[nt]) << 2)];
      }
#pragma unroll
      for (int mt = 0; mt < 4; mt++)
#pragma unroll
        for (int nt = 0; nt < 4; nt++)
          mma_tf32(acc[mt][nt], af[mt], bf[nt]);
    }
  }

  // epilogue
#pragma unroll
  for (int mt = 0; mt < 4; mt++) {
    const int row = bm + wm + mt * 16 + g;
#pragma unroll
    for (int nt = 0; nt < 4; nt++) {
      const int col = bn + wn + nt * 8 + 2 * tig;
      *(float2*)(C + (size_t)row * N + col)       = make_float2(acc[mt][nt][0], acc[mt][nt][1]);
      *(float2*)(C + (size_t)(row + 8) * N + col) = make_float2(acc[mt][nt][2], acc[mt][nt][3]);
    }
  }
}

// ---------------------------------------------------------------------------
// RMSNorm: out = x * rsqrt(mean(x^2)+eps) * w, rounded to tf32 for next GEMM.
// ---------------------------------------------------------------------------
__global__ void __launch_bounds__(256) rmsnorm_kernel(
    const float* __restrict__ in, const float* __restrict__ w,
    float* __restrict__ out, int n, int istride, int ostride) {
  const int row = blockIdx.x;
  const float* x = in + (size_t)row * istride;
  float s = 0.f;
  for (int i = threadIdx.x; i < n; i += 256) { float v = x[i]; s += v*v; }
  __shared__ float red[256];
  red[threadIdx.x] = s;
  __syncthreads();
  for (int off = 128; off > 0; off >>= 1) {
    if (threadIdx.x < off) red[threadIdx.x] += red[threadIdx.x + off];
    __syncthreads();
  }
  const float inv = rsqrtf(red[0] / (float)n + EPS);
  float* o = out + (size_t)row * ostride;
  for (int i = threadIdx.x; i < n; i += 256) o[i] = rtf(x[i] * inv * w[i]);
}

// ---------------------------------------------------------------------------
// RoPE on q_pe (in-place in g_q).
// ---------------------------------------------------------------------------
__global__ void rope_q_kernel(float* __restrict__ q,
                              const float* __restrict__ cosb,
                              const float* __restrict__ sinb) {
  int idx = blockIdx.x * blockDim.x + threadIdx.x;   // SQ*NH*32
  int d = idx & 31;
  int h = (idx >> 5) & (NH - 1);
  int s = idx >> 12;
  float* base = q + (size_t)s * HDQ + h * DQH + DNOPE;
  float x1 = base[d], x2 = base[d + 32];
  float c1 = cosb[s*DROPE + d],      s1 = sinb[s*DROPE + d];
  float c2 = cosb[s*DROPE + d + 32], s2 = sinb[s*DROPE + d + 32];
  base[d]      = x1*c1 - x2*s1;
  base[d + 32] = x2*c2 + x1*s2;
}

// RoPE on k_pe (from qkva cols [2048, 2112)) -> g_kpe[S, 64]
__global__ void rope_k_kernel(const float* __restrict__ qkva,
                              const float* __restrict__ cosb,
                              const float* __restrict__ sinb,
                              float* __restrict__ kpe) {
  int idx = blockIdx.x * blockDim.x + threadIdx.x;  // SQ*32
  int d = idx & 31;
  int s = idx >> 5;
  float x1 = qkva[(size_t)s*NCAT + (RQ+RKV) + d];
  float x2 = qkva[(size_t)s*NCAT + (RQ+RKV) + 32 + d];
  float c1 = cosb[s*DROPE + d],      s1 = sinb[s*DROPE + d];
  float c2 = cosb[s*DROPE + d + 32], s2 = sinb[s*DROPE + d + 32];
  kpe[s*DROPE + d]      = x1*c1 - x2*s1;
  kpe[s*DROPE + 32 + d] = x2*c2 + x1*s2;
}

// ---------------------------------------------------------------------------
// Flash attention (causal), register-blocked. One block per (head, 64-row q
// tile), 256 threads as a 16x16 grid: thread (ty,tx) owns a 4x4 score tile
// (rows ty*4.., cols tx*4..) and a 4x8 output tile (cols tx*8..).
// Softmax row-reduction via shfl over the 16-lane tx group. fp32 throughout;
// output rounded to tf32 (feeds the wo GEMM).
// NOTE: Ps has odd word stride (65) for conflict-free PV reads -> P values are
// written with SCALAR stores (float4 would be misaligned: 65*4 B row base).
// ---------------------------------------------------------------------------
#define QK_STR 196
#define PS_STR 65
#define FLASH_SMEM ((2*64*QK_STR + 64*128 + 64*PS_STR) * 4)

__global__ void __launch_bounds__(256) flash_kernel(
    const float* __restrict__ q, const float* __restrict__ kv,
    const float* __restrict__ kpe, float* __restrict__ ao) {
  extern __shared__ float smf[];
  float* Qs = smf;                     // 64 x QK_STR
  float* Ks = Qs + 64*QK_STR;          // 64 x QK_STR
  float* Vs = Ks + 64*QK_STR;          // 64 x 128
  float* Ps = Vs + 64*128;             // 64 x PS_STR

  const int h  = blockIdx.x;
  const int q0 = blockIdx.y * 64;
  const int tid = threadIdx.x;
  const int tx = tid & 15;
  const int ty = tid >> 4;
  const int r0 = ty * 4;               // q-row group
  const int c0 = tx * 4;               // score-col group
  const int oc = tx * 8;               // out-col group

  for (int idx = tid; idx < 64*DQH; idx += 256) {
    int row = idx / DQH, d = idx % DQH;
    Qs[row*QK_STR + d] = q[(size_t)(q0+row)*HDQ + h*DQH + d];
  }

  float m[4], l[4], o[4][8];
#pragma unroll
  for (int r = 0; r < 4; r++) {
    m[r] = -INFINITY; l[r] = 0.f;
#pragma unroll
    for (int c = 0; c < 8; c++) o[r][c] = 0.f;
  }
  const float scale = rsqrtf((float)DQH);

  const int nkt = blockIdx.y + 1;
  for (int kt = 0; kt < nkt; kt++) {
    const int k0 = kt * 64;
    __syncthreads();
    for (int idx = tid; idx < 64*DQH; idx += 256) {
      int row = idx / DQH, d = idx % DQH;
      Ks[row*QK_STR + d] = (d < DNOPE)
          ? kv[(size_t)(k0+row)*HKV + h*(DNOPE+DVAL) + d]
          : kpe[(k0+row)*DROPE + (d - DNOPE)];
    }
    for (int idx = tid; idx < 64*128; idx += 256) {
      int row = idx >> 7, d = idx & 127;
      Vs[idx] = kv[(size_t)(k0+row)*HKV + h*(DNOPE+DVAL) + DNOPE + d];
    }
    __syncthreads();

    // scores: 4x4 microtile, float4 over d
    float sc[4][4];
#pragma unroll
    for (int r = 0; r < 4; r++)
#pragma unroll
      for (int c = 0; c < 4; c++) sc[r][c] = 0.f;

    for (int d0 = 0; d0 < DQH; d0 += 4) {
      float4 qv[4], kv4[4];
#pragma unroll
      for (int r = 0; r < 4; r++) qv[r]  = *(const float4*)&Qs[(r0+r)*QK_STR + d0];
#pragma unroll
      for (int c = 0; c < 4; c++) kv4[c] = *(const float4*)&Ks[(c0+c)*QK_STR + d0];
#pragma unroll
      for (int r = 0; r < 4; r++)
#pragma unroll
        for (int c = 0; c < 4; c++) {
          sc[r][c] += qv[r].x*kv4[c].x + qv[r].y*kv4[c].y
                    + qv[r].z*kv4[c].z + qv[r].w*kv4[c].w;
        }
    }

    if (kt == nkt - 1) {     // only the diagonal tile needs the causal mask
#pragma unroll
      for (int r = 0; r < 4; r++)
#pragma unroll
        for (int c = 0; c < 4; c++)
          sc[r][c] = (k0 + c0 + c <= q0 + r0 + r) ? sc[r][c]*scale : -INFINITY;
    } else {
#pragma unroll
      for (int r = 0; r < 4; r++)
#pragma unroll
        for (int c = 0; c < 4; c++) sc[r][c] *= scale;
    }

    // online softmax: reduce over tx (16 lanes)
    float alpha[4];
#pragma unroll
    for (int r = 0; r < 4; r++) {
      float mloc = fmaxf(fmaxf(sc[r][0], sc[r][1]), fmaxf(sc[r][2], sc[r][3]));
      mloc = fmaxf(mloc, __shfl_xor_sync(0xffffffffu, mloc, 1));
      mloc = fmaxf(mloc, __shfl_xor_sync(0xffffffffu, mloc, 2));
      mloc = fmaxf(mloc, __shfl_xor_sync(0xffffffffu, mloc, 4));
      mloc = fmaxf(mloc, __shfl_xor_sync(0xffffffffu, mloc, 8));
      float mnew = fmaxf(m[r], mloc);
      alpha[r] = expf(m[r] - mnew);
      float lloc = 0.f;
#pragma unroll
      for (int c = 0; c < 4; c++) {
        float p = expf(sc[r][c] - mnew);
        sc[r][c] = p;
        lloc += p;
      }
      lloc += __shfl_xor_sync(0xffffffffu, lloc, 1);
      lloc += __shfl_xor_sync(0xffffffffu, lloc, 2);
      lloc += __shfl_xor_sync(0xffffffffu, lloc, 4);
      lloc += __shfl_xor_sync(0xffffffffu, lloc, 8);
      l[r] = l[r] * alpha[r] + lloc;
      m[r] = mnew;
#pragma unroll
      for (int c = 0; c < 8; c++) o[r][c] *= alpha[r];
      // scalar stores: Ps row stride 65 words is not 16B-aligned
      Ps[(r0+r)*PS_STR + c0    ] = sc[r][0];
      Ps[(r0+r)*PS_STR + c0 + 1] = sc[r][1];
      Ps[(r0+r)*PS_STR + c0 + 2] = sc[r][2];
      Ps[(r0+r)*PS_STR + c0 + 3] = sc[r][3];
    }
    __syncthreads();   // Ps visible to all before PV

    // PV: thread accumulates rows r0..r0+3 x cols oc..oc+7
    for (int j = 0; j < 64; j++) {
      float4 v0 = *(const float4*)&Vs[j*128 + oc];
      float4 v1 = *(const float4*)&Vs[j*128 + oc + 4];
      float pv[4];
#pragma unroll
      for (int r = 0; r < 4; r++) pv[r] = Ps[(r0+r)*PS_STR + j];
#pragma unroll
      for (int r = 0; r < 4; r++) {
        o[r][0] += pv[r]*v0.x; o[r][1] += pv[r]*v0.y;
        o[r][2] += pv[r]*v0.z; o[r][3] += pv[r]*v0.w;
        o[r][4] += pv[r]*v1.x; o[r][5] += pv[r]*v1.y;
        o[r][6] += pv[r]*v1.z; o[r][7] += pv[r]*v1.w;
      }
    }
  }

#pragma unroll
  for (int r = 0; r < 4; r++) {
    const float invl = 1.f / l[r];
    float* op = ao + (size_t)(q0 + r0 + r)*HDV + h*DVAL + oc;
#pragma unroll
    for (int c = 0; c < 8; c++) op[c] = rtf(o[r][c] * invl);
  }
}

// ---------------------------------------------------------------------------
extern "C" void kernel_launch(void* const* d_in, const int* in_sizes, int n_in,
                              void* d_out, int out_size) {
  const float* hidden  = (const float*)d_in[0];
  const float* cosb    = (const float*)d_in[1];
  const float* sinb    = (const float*)d_in[2];
  const float* wq_a    = (const float*)d_in[3];
  const float* q_ln_w  = (const float*)d_in[4];
  const float* wq_b    = (const float*)d_in[5];
  const float* wkv_a   = (const float*)d_in[6];
  const float* kv_ln_w = (const float*)d_in[7];
  const float* wkv_b   = (const float*)d_in[8];
  const float* wo      = (const float*)d_in[9];
  float* out = (float*)d_out;

  float *hid, *wqkva, *qkva, *qan, *wqb, *q, *kvn, *wkvb, *kv, *kpe, *ao, *woR;
  cudaGetSymbolAddress((void**)&hid,   g_hid);
  cudaGetSymbolAddress((void**)&wqkva, g_wqkva);
  cudaGetSymbolAddress((void**)&qkva,  g_qkva);
  cudaGetSymbolAddress((void**)&qan,   g_qan);
  cudaGetSymbolAddress((void**)&wqb,   g_wqb);
  cudaGetSymbolAddress((void**)&q,     g_q);
  cudaGetSymbolAddress((void**)&kvn,   g_kvn);
  cudaGetSymbolAddress((void**)&wkvb,  g_wkvb);
  cudaGetSymbolAddress((void**)&kv,    g_kv);
  cudaGetSymbolAddress((void**)&kpe,   g_kpe);
  cudaGetSymbolAddress((void**)&ao,    g_ao);
  cudaGetSymbolAddress((void**)&woR,   g_wo);

  cudaFuncSetAttribute(gemm_tf32_cp, cudaFuncAttributeMaxDynamicSharedMemorySize,
                       STAGES * 2 * AW * 4);
  cudaFuncSetAttribute(flash_kernel, cudaFuncAttributeMaxDynamicSharedMemorySize, FLASH_SMEM);

  // pre-round operands to tf32 values (rna), re-layout wq_a||wkv_a into padded concat
  auto rnd = [](const float* s, float* d, int n) {
    round4_kernel<<<(n/4 + 255)/256, 256>>>((const float4*)s, (float4*)d, n/4);
  };
  rnd(hidden, hid,   SQ*DIM);
  rnd(wq_a,   wqkva, RQ*DIM);
  rnd(wkv_a,  wqkva + (size_t)RQ*DIM, (RKV+DROPE)*DIM);   // rows 2112..2175 stay 0
  rnd(wq_b,   wqb,   HDQ*RQ);
  rnd(wkv_b,  wkvb,  HKV*RKV);
  rnd(wo,     woR,   DIM*HDV);

  const int GSM = STAGES * 2 * AW * 4;

  // fused q_a + kv_a projection: qkva[1024, 2176]
  gemm_tf32_cp<<<dim3(SQ/128, NCAT/128), 256, GSM>>>(hid, wqkva, qkva, SQ, NCAT, DIM);

  // q path
  rmsnorm_kernel<<<SQ, 256>>>(qkva, q_ln_w, qan, RQ, NCAT, RQ);
  gemm_tf32_cp<<<dim3(SQ/128, HDQ/128), 256, GSM>>>(qan, wqb, q, SQ, HDQ, RQ);

  // kv path
  rmsnorm_kernel<<<SQ, 256>>>(qkva + RQ, kv_ln_w, kvn, RKV, NCAT, RKV);
  gemm_tf32_cp<<<dim3(SQ/128, HKV/128), 256, GSM>>>(kvn, wkvb, kv, SQ, HKV, RKV);

  // RoPE
  rope_q_kernel<<<(SQ*NH*32)/256, 256>>>(q, cosb, sinb);
  rope_k_kernel<<<(SQ*32)/256, 256>>>(qkva, cosb, sinb, kpe);

  // causal flash attention (rounds its output)
  flash_kernel<<<dim3(NH, SQ/64), 256, FLASH_SMEM>>>(q, kv, kpe, ao);

  // output projection
  gemm_tf32_cp<<<dim3(SQ/128, DIM/128), 256, GSM>>>(ao, woR, out, SQ, DIM, HDV);
}